// round 6
// baseline (speedup 1.0000x reference)
#include <cuda_runtime.h>
#include <cuda_bf16.h>

// FlowCPAB: per-bin linear interpolation of the exact closed-form map.
// Each block rebuilds (in shared) the per-cell CPAB algebra:
//   segments where  u = FL ? log|x+C0| : x,
//                   z = C1*exp(G*u) + C4*u + C2,   ld = D1*u + D2
// then tabulates z(x), ld(x) at 1281 nodes and stores per-bin {z0,dz,ld0,dld}.
// z is C1 (z' = e^ld continuous), ld is C0; NB is a multiple of 5 so cell
// boundaries land on bin edges. Bins containing an interior threshold (ld-kink)
// are flagged (dz=1e30) and evaluated with the exact closed form instead.
// NB=1280: interp error ~ f''*h^2/8 ~ 8e-8*f'' << 1e-3 tolerance, and the
// 20KB table allows 8 blocks/SM (full warp occupancy).

#define NC 5
#define EPSC 1e-7f
#define NB 1280              // 5 * 256 bins
#define FNB 1280.0f

__device__ __forceinline__ void exact_eval(float x, float& z, float& ld,
                                           const float* __restrict__ thr,
                                           const float4* __restrict__ cf)
{
    x = fminf(fmaxf(x, EPSC), 1.0f - EPSC);
    const int c = min(NC - 1, (int)(x * 5.0f));
    int mm = 0;
#pragma unroll
    for (int k = 0; k < 8; ++k) mm += (thr[c * 8 + k] < x) ? 1 : 0;
    const int seg = c * 9 + mm;
    const float4 c1 = cf[seg * 2];          // {C0, G, C1, C4}
    const float4 c2 = cf[seg * 2 + 1];      // {C2, D1, D2, FL}
    const float u = (c2.w != 0.0f) ? __logf(fabsf(x + c1.x)) : x;
    const float e = __expf(c1.y * u);
    z  = fmaf(c1.z, e, fmaf(c1.w, u, c2.x));
    ld = fmaf(c2.y, u, c2.z);
}

__device__ __forceinline__ void interp_point(float x, float& z, float& ld,
                                             const float4* __restrict__ s_bin,
                                             const float* __restrict__ s_thr,
                                             const float4* __restrict__ s_cf)
{
    x = fminf(fmaxf(x, EPSC), 1.0f - EPSC);
    const float xf = x * FNB;
    const int bin = (int)xf;
    const float fr = xf - (float)bin;
    const float4 nb = s_bin[bin];
    if (fabsf(nb.y) > 1e3f) {
        exact_eval(x, z, ld, s_thr, s_cf);
    } else {
        z  = fmaf(fr, nb.y, nb.x);
        ld = fmaf(fr, nb.w, nb.z);
    }
}

__global__ void __launch_bounds__(256)
flowcpab_fused(const float* __restrict__ xin,
               const float* __restrict__ theta,
               const float* __restrict__ Bm,
               float* __restrict__ out, int n)
{
    __shared__ float  s_thr[NC * 8];
    __shared__ float4 s_cf[NC * 9 * 2];
    __shared__ float4 s_bin[NB];
    __shared__ float A[5], Bc[5], BOA[5], SBv[5];
    __shared__ int   BIGF[5];
    __shared__ float TAUR[5], TAUL[5], LDRv[5], LDLv[5];
    __shared__ float TR[6][6], TLm[6][6], LRm[6][6], LLm[6][6];
    __shared__ int   NT[5];

    const int tid = threadIdx.x;

    // ---- Phase A: per-cell (a,b) and traversal times ----
    if (tid < 5) {
        float a = 0.f, b = 0.f;
#pragma unroll
        for (int k = 0; k < 6; ++k) {
            a += Bm[(2 * tid) * 6 + k]     * theta[k];
            b += Bm[(2 * tid + 1) * 6 + k] * theta[k];
        }
        A[tid] = a; Bc[tid] = b;
        const int big = fabsf(a) > 1e-8f;
        BIGF[tid] = big;
        const float sa  = big ? a : 1.0f;
        const float sb  = (fabsf(b) > 1e-12f) ? b : 1e-12f;
        const float boa = b / sa;
        SBv[tid] = sb; BOA[tid] = boa;
        const float xl = tid / 5.0f, xr = (tid + 1) / 5.0f;
        {
            const float v = a * xl + b, den = xl + boa;
            const float sden = (fabsf(den) > 1e-12f) ? den : 1e-12f;
            const float ratio = (xr + boa) / sden;
            const float th = big ? logf(fmaxf(ratio, 1e-12f)) / sa : (xr - xl) / sb;
            const int valid = (fabsf(v) > 1e-12f) && (th >= 0.f) && (!big || ratio > 0.f);
            TAUR[tid] = valid ? th : 1e10f;
            LDRv[tid] = valid ? a * th : 0.f;
        }
        {
            const float v = a * xr + b, den = xr + boa;
            const float sden = (fabsf(den) > 1e-12f) ? den : 1e-12f;
            const float ratio = (xl + boa) / sden;
            const float th = big ? logf(fmaxf(ratio, 1e-12f)) / sa : (xl - xr) / sb;
            const int valid = (fabsf(v) > 1e-12f) && (th >= 0.f) && (!big || ratio > 0.f);
            TAUL[tid] = valid ? th : 1e10f;
            LDLv[tid] = valid ? a * th : 0.f;
        }
    }
    __syncthreads();

    // ---- Phase B: cumulative chain tables per boundary ----
    if (tid < 12) {
        const int j = tid % 6, dir = tid / 6;
        float tc = 0.f, lc = 0.f;
        if (dir == 0) {
            TR[j][0] = 0.f; LRm[j][0] = 0.f;
            for (int m = 1; m <= 5; ++m) {
                const int cell = j + m - 1;
                if (cell <= 4 && tc < 1e9f && TAUR[cell] < 1e9f) { tc += TAUR[cell]; lc += LDRv[cell]; }
                else tc = 1e10f;
                TR[j][m] = tc; LRm[j][m] = lc;
            }
        } else {
            TLm[j][0] = 0.f; LLm[j][0] = 0.f;
            for (int m = 1; m <= 5; ++m) {
                const int cell = j - m;
                if (cell >= 0 && tc < 1e9f && TAUL[cell] < 1e9f) { tc += TAUL[cell]; lc += LDLv[cell]; }
                else tc = 1e10f;
                TLm[j][m] = tc; LLm[j][m] = lc;
            }
        }
    }
    __syncthreads();

    // ---- Phase C: per-cell thresholds ----
    if (tid < 5) {
        const int c = tid;
        const float a = A[c], b = Bc[c], boa = BOA[c], sb = SBv[c];
        const int big = BIGF[c];
        const float xl = c / 5.0f, xr = (c + 1) / 5.0f;
        float cand[16]; int ncand = 0;
        if (big) {
            const float xs = -boa;
            if (xs > xl && xs < xr) cand[ncand++] = xs;
        }
        for (int dir = 0; dir < 2; ++dir) {
            const int jb = (dir == 0) ? c + 1 : c;
            const float xb = jb / 5.0f;
            const float* Tc = (dir == 0) ? TR[jb] : TLm[jb];
            for (int m = 0; m <= 5; ++m) {
                const float th = (m == 0) ? 1.0f : (1.0f - Tc[m]);
                if (!(th > 0.f && th <= 1.0f)) continue;
                const float xt = big ? (xb + boa) * expf(-a * th) - boa
                                     : xb - sb * th;
                if (xt > xl && xt < xr) {
                    const float v = a * xt + b;
                    const int r = (v >= 0.f);
                    if ((r && dir == 0) || (!r && dir == 1))
                        if (ncand < 16) cand[ncand++] = xt;
                }
            }
        }
        for (int i = 1; i < ncand; ++i) {
            float v = cand[i]; int j = i - 1;
            while (j >= 0 && cand[j] > v) { cand[j + 1] = cand[j]; --j; }
            cand[j + 1] = v;
        }
        int nt = 0;
        float last = -1.f;
        for (int i = 0; i < ncand && nt < 8; ++i)
            if (nt == 0 || cand[i] - last > 1e-9f) { last = cand[i]; s_thr[c * 8 + nt] = last; ++nt; }
        NT[c] = nt;
        for (int k = nt; k < 8; ++k) s_thr[c * 8 + k] = 1e30f;
    }
    __syncthreads();

    // ---- Phase D: per-segment coefficients ----
    if (tid < 45) {
        const int c = tid / 9, sgi = tid % 9;
        const int nt = NT[c];
        float C0 = 0, FL = 0, G = 0, C1 = 0, C4 = 0, C2 = 0, D1 = 0, D2 = 0;
        if (sgi <= nt) {
            const float xl = c / 5.0f, xr = (c + 1) / 5.0f;
            const float lo = (sgi == 0) ? xl : s_thr[c * 8 + sgi - 1];
            const float hi = (sgi == nt) ? xr : s_thr[c * 8 + sgi];
            const float xm = 0.5f * (lo + hi);
            const float a = A[c], b = Bc[c], boa = BOA[c], sb = SBv[c];
            const int big = BIGF[c];
            const float v = a * xm + b;
            const float den = xm + boa;
            const float sden = (fabsf(den) > 1e-12f) ? den : 1e-12f;
            const int right = (v >= 0.f);
            const int jb = right ? c + 1 : c;
            const float xb = jb / 5.0f;
            const float ratio = (xb + boa) / sden;
            const float thit = big ? logf(fmaxf(ratio, 1e-12f)) / a : (xb - xm) / sb;
            const int valid = (fabsf(v) > 1e-12f) && (thit >= 0.f) && (!big || ratio > 0.f);
            if (!valid || thit >= 1.0f) {
                if (big) { const float ea = expf(a); C4 = ea; C2 = boa * (ea - 1.0f); }
                else     { C4 = 1.0f; C2 = b; }
                D2 = a;
            } else {
                const float s = 1.0f - thit;
                const float* Tc = right ? TR[jb] : TLm[jb];
                const float* Lc = right ? LRm[jb] : LLm[jb];
                int mm = 0;
                for (int m = 1; m <= 5; ++m) mm += (Tc[m] < s) ? 1 : 0;
                const float Lcum = Lc[mm], Tmm = Tc[mm];
                const int jb2 = right ? jb + mm : jb - mm;
                float P, Q;
                if (big) { FL = 1.0f; C0 = boa; P = logf(fabsf(xb + boa)) / a; Q = 1.0f / a; }
                else     { FL = 0.0f; C0 = 0.0f; P = xb / sb; Q = 1.0f / sb; }
                const float S0 = 1.0f - Tmm - P;
                const int absorbed = right ? (jb2 == 5) : (jb2 == 0);
                if (absorbed) {
                    C2 = right ? 1.0f : 0.0f;
                    D1 = -a * Q; D2 = a * P + Lcum;
                } else {
                    const int cc = right ? jb2 : jb2 - 1;
                    const float x0 = jb2 / 5.0f;
                    const float a2 = A[cc], b2 = Bc[cc];
                    if (fabsf(a2) > 1e-8f) {
                        const float boa2 = b2 / a2;
                        G = a2 * Q; C1 = (x0 + boa2) * expf(a2 * S0); C2 = -boa2;
                    } else {
                        C4 = b2 * Q; C2 = x0 + b2 * S0;
                    }
                    D1 = (a2 - a) * Q; D2 = a * P + Lcum + a2 * S0;
                }
            }
        }
        s_cf[tid * 2]     = make_float4(C0, G, C1, C4);
        s_cf[tid * 2 + 1] = make_float4(C2, D1, D2, FL);
    }
    __syncthreads();

    // ---- Phase E: build bin table ----
    for (int j = tid; j < NB; j += blockDim.x) {
        const float x0 = (float)j / FNB;
        const float x1 = (float)(j + 1) / FNB;
        float z0, l0, z1, l1;
        exact_eval(x0, z0, l0, s_thr, s_cf);
        exact_eval(x1, z1, l1, s_thr, s_cf);
        const int c = j / (NB / 5);
        bool mixed = false;
#pragma unroll
        for (int k = 0; k < 8; ++k) {
            const float t = s_thr[c * 8 + k];
            mixed = mixed || (t > x0 && t < x1);
        }
        float4 e;
        e.x = z0;
        e.y = mixed ? 1e30f : (z1 - z0);
        e.z = l0;
        e.w = mixed ? 0.0f : (l1 - l0);
        s_bin[j] = e;
    }
    __syncthreads();

    // ---- Phase F: stream points, 8 per thread-iteration for ILP ----
    const int gtid   = blockIdx.x * blockDim.x + tid;
    const int stride = gridDim.x * blockDim.x;

    if ((n & 3) == 0) {
        const int n4 = n >> 2;
        const float4* __restrict__ x4 = (const float4*)xin;
        float4* __restrict__ z4 = (float4*)out;
        float4* __restrict__ l4 = (float4*)(out + n);

        int i = gtid;
        // paired iterations: two independent LDG.128 chains in flight
        for (; i + stride < n4; i += 2 * stride) {
            const float4 xa = x4[i];
            const float4 xb = x4[i + stride];
            float4 za, la, zb, lb;
            interp_point(xa.x, za.x, la.x, s_bin, s_thr, s_cf);
            interp_point(xa.y, za.y, la.y, s_bin, s_thr, s_cf);
            interp_point(xa.z, za.z, la.z, s_bin, s_thr, s_cf);
            interp_point(xa.w, za.w, la.w, s_bin, s_thr, s_cf);
            interp_point(xb.x, zb.x, lb.x, s_bin, s_thr, s_cf);
            interp_point(xb.y, zb.y, lb.y, s_bin, s_thr, s_cf);
            interp_point(xb.z, zb.z, lb.z, s_bin, s_thr, s_cf);
            interp_point(xb.w, zb.w, lb.w, s_bin, s_thr, s_cf);
            z4[i] = za;            l4[i] = la;
            z4[i + stride] = zb;   l4[i + stride] = lb;
        }
        for (; i < n4; i += stride) {
            const float4 xv = x4[i];
            float4 zv, lv;
            interp_point(xv.x, zv.x, lv.x, s_bin, s_thr, s_cf);
            interp_point(xv.y, zv.y, lv.y, s_bin, s_thr, s_cf);
            interp_point(xv.z, zv.z, lv.z, s_bin, s_thr, s_cf);
            interp_point(xv.w, zv.w, lv.w, s_bin, s_thr, s_cf);
            z4[i] = zv;
            l4[i] = lv;
        }
    } else {
        for (int i = gtid; i < n; i += stride) {
            float z, ld;
            interp_point(xin[i], z, ld, s_bin, s_thr, s_cf);
            out[i] = z;
            out[n + i] = ld;
        }
    }
}

extern "C" void kernel_launch(void* const* d_in, const int* in_sizes, int n_in,
                              void* d_out, int out_size)
{
    const float* x     = (const float*)d_in[0];
    const float* theta = (const float*)d_in[1];
    const float* Bm    = (const float*)d_in[2];
    float* out = (float*)d_out;
    const int n = in_sizes[0];

    const int threads = 256;
    int blocks = 1184;                   // 148 SMs * 8 resident blocks (~22KB smem each)
    int work = ((n & 3) == 0) ? (n >> 2) : n;
    int maxb = (work + threads - 1) / threads;
    if (blocks > maxb) blocks = maxb;
    if (blocks < 1) blocks = 1;
    flowcpab_fused<<<blocks, threads>>>(x, theta, Bm, out, n);
}

// round 7
// speedup vs baseline: 1.7399x; 1.7399x over previous
#include <cuda_runtime.h>
#include <cuda_bf16.h>

// FlowCPAB: per-bin linear interpolation of the exact closed-form map.
// Each block rebuilds (in shared) the per-cell CPAB algebra:
//   segments where  u = FL ? log|x+C0| : x,
//                   z = C1*exp(G*u) + C4*u + C2,   ld = D1*u + D2
// then tabulates z(x), ld(x) at 1281 nodes and stores per-bin {z0,dz,ld0,dld}.
// Bins containing an interior threshold (ld-kink) are flagged and evaluated
// with the exact closed form. NB multiple of 5 so cell boundaries land on bin
// edges; interp error ~ f''/8 * (1/1280)^2 ~ 8e-8*f'' << 1e-3 tolerance.
// Grid is sized at runtime to EXACTLY (resident blocks/SM) * SMs: the
// grid-stride work split is even per block, so any extra wave doubles runtime
// (measured R6 regression). __launch_bounds__(256,8) keeps regs <= 32.

#define NC 5
#define EPSC 1e-7f
#define NB 1280              // 5 * 256 bins
#define FNB 1280.0f

__device__ __forceinline__ void exact_eval(float x, float& z, float& ld,
                                           const float* __restrict__ thr,
                                           const float4* __restrict__ cf)
{
    x = fminf(fmaxf(x, EPSC), 1.0f - EPSC);
    const int c = min(NC - 1, (int)(x * 5.0f));
    int mm = 0;
#pragma unroll
    for (int k = 0; k < 8; ++k) mm += (thr[c * 8 + k] < x) ? 1 : 0;
    const int seg = c * 9 + mm;
    const float4 c1 = cf[seg * 2];          // {C0, G, C1, C4}
    const float4 c2 = cf[seg * 2 + 1];      // {C2, D1, D2, FL}
    const float u = (c2.w != 0.0f) ? __logf(fabsf(x + c1.x)) : x;
    const float e = __expf(c1.y * u);
    z  = fmaf(c1.z, e, fmaf(c1.w, u, c2.x));
    ld = fmaf(c2.y, u, c2.z);
}

__device__ __forceinline__ void interp_point(float x, float& z, float& ld,
                                             const float4* __restrict__ s_bin,
                                             const float* __restrict__ s_thr,
                                             const float4* __restrict__ s_cf)
{
    x = fminf(fmaxf(x, EPSC), 1.0f - EPSC);
    const float xf = x * FNB;
    const int bin = (int)xf;
    const float fr = xf - (float)bin;
    const float4 nb = s_bin[bin];
    if (fabsf(nb.y) > 1e3f) {
        exact_eval(x, z, ld, s_thr, s_cf);
    } else {
        z  = fmaf(fr, nb.y, nb.x);
        ld = fmaf(fr, nb.w, nb.z);
    }
}

__global__ void __launch_bounds__(256, 8)
flowcpab_fused(const float* __restrict__ xin,
               const float* __restrict__ theta,
               const float* __restrict__ Bm,
               float* __restrict__ out, int n)
{
    __shared__ float  s_thr[NC * 8];
    __shared__ float4 s_cf[NC * 9 * 2];
    __shared__ float4 s_bin[NB];
    __shared__ float A[5], Bc[5], BOA[5], SBv[5];
    __shared__ int   BIGF[5];
    __shared__ float TAUR[5], TAUL[5], LDRv[5], LDLv[5];
    __shared__ float TR[6][6], TLm[6][6], LRm[6][6], LLm[6][6];
    __shared__ int   NT[5];

    const int tid = threadIdx.x;

    // ---- Phase A: per-cell (a,b) and traversal times ----
    if (tid < 5) {
        float a = 0.f, b = 0.f;
#pragma unroll
        for (int k = 0; k < 6; ++k) {
            a += Bm[(2 * tid) * 6 + k]     * theta[k];
            b += Bm[(2 * tid + 1) * 6 + k] * theta[k];
        }
        A[tid] = a; Bc[tid] = b;
        const int big = fabsf(a) > 1e-8f;
        BIGF[tid] = big;
        const float sa  = big ? a : 1.0f;
        const float sb  = (fabsf(b) > 1e-12f) ? b : 1e-12f;
        const float boa = b / sa;
        SBv[tid] = sb; BOA[tid] = boa;
        const float xl = tid / 5.0f, xr = (tid + 1) / 5.0f;
        {
            const float v = a * xl + b, den = xl + boa;
            const float sden = (fabsf(den) > 1e-12f) ? den : 1e-12f;
            const float ratio = (xr + boa) / sden;
            const float th = big ? logf(fmaxf(ratio, 1e-12f)) / sa : (xr - xl) / sb;
            const int valid = (fabsf(v) > 1e-12f) && (th >= 0.f) && (!big || ratio > 0.f);
            TAUR[tid] = valid ? th : 1e10f;
            LDRv[tid] = valid ? a * th : 0.f;
        }
        {
            const float v = a * xr + b, den = xr + boa;
            const float sden = (fabsf(den) > 1e-12f) ? den : 1e-12f;
            const float ratio = (xl + boa) / sden;
            const float th = big ? logf(fmaxf(ratio, 1e-12f)) / sa : (xl - xr) / sb;
            const int valid = (fabsf(v) > 1e-12f) && (th >= 0.f) && (!big || ratio > 0.f);
            TAUL[tid] = valid ? th : 1e10f;
            LDLv[tid] = valid ? a * th : 0.f;
        }
    }
    __syncthreads();

    // ---- Phase B: cumulative chain tables per boundary ----
    if (tid < 12) {
        const int j = tid % 6, dir = tid / 6;
        float tc = 0.f, lc = 0.f;
        if (dir == 0) {
            TR[j][0] = 0.f; LRm[j][0] = 0.f;
            for (int m = 1; m <= 5; ++m) {
                const int cell = j + m - 1;
                if (cell <= 4 && tc < 1e9f && TAUR[cell] < 1e9f) { tc += TAUR[cell]; lc += LDRv[cell]; }
                else tc = 1e10f;
                TR[j][m] = tc; LRm[j][m] = lc;
            }
        } else {
            TLm[j][0] = 0.f; LLm[j][0] = 0.f;
            for (int m = 1; m <= 5; ++m) {
                const int cell = j - m;
                if (cell >= 0 && tc < 1e9f && TAUL[cell] < 1e9f) { tc += TAUL[cell]; lc += LDLv[cell]; }
                else tc = 1e10f;
                TLm[j][m] = tc; LLm[j][m] = lc;
            }
        }
    }
    __syncthreads();

    // ---- Phase C: per-cell thresholds ----
    if (tid < 5) {
        const int c = tid;
        const float a = A[c], b = Bc[c], boa = BOA[c], sb = SBv[c];
        const int big = BIGF[c];
        const float xl = c / 5.0f, xr = (c + 1) / 5.0f;
        float cand[16]; int ncand = 0;
        if (big) {
            const float xs = -boa;
            if (xs > xl && xs < xr) cand[ncand++] = xs;
        }
        for (int dir = 0; dir < 2; ++dir) {
            const int jb = (dir == 0) ? c + 1 : c;
            const float xb = jb / 5.0f;
            const float* Tc = (dir == 0) ? TR[jb] : TLm[jb];
            for (int m = 0; m <= 5; ++m) {
                const float th = (m == 0) ? 1.0f : (1.0f - Tc[m]);
                if (!(th > 0.f && th <= 1.0f)) continue;
                const float xt = big ? (xb + boa) * expf(-a * th) - boa
                                     : xb - sb * th;
                if (xt > xl && xt < xr) {
                    const float v = a * xt + b;
                    const int r = (v >= 0.f);
                    if ((r && dir == 0) || (!r && dir == 1))
                        if (ncand < 16) cand[ncand++] = xt;
                }
            }
        }
        for (int i = 1; i < ncand; ++i) {
            float v = cand[i]; int j = i - 1;
            while (j >= 0 && cand[j] > v) { cand[j + 1] = cand[j]; --j; }
            cand[j + 1] = v;
        }
        int nt = 0;
        float last = -1.f;
        for (int i = 0; i < ncand && nt < 8; ++i)
            if (nt == 0 || cand[i] - last > 1e-9f) { last = cand[i]; s_thr[c * 8 + nt] = last; ++nt; }
        NT[c] = nt;
        for (int k = nt; k < 8; ++k) s_thr[c * 8 + k] = 1e30f;
    }
    __syncthreads();

    // ---- Phase D: per-segment coefficients ----
    if (tid < 45) {
        const int c = tid / 9, sgi = tid % 9;
        const int nt = NT[c];
        float C0 = 0, FL = 0, G = 0, C1 = 0, C4 = 0, C2 = 0, D1 = 0, D2 = 0;
        if (sgi <= nt) {
            const float xl = c / 5.0f, xr = (c + 1) / 5.0f;
            const float lo = (sgi == 0) ? xl : s_thr[c * 8 + sgi - 1];
            const float hi = (sgi == nt) ? xr : s_thr[c * 8 + sgi];
            const float xm = 0.5f * (lo + hi);
            const float a = A[c], b = Bc[c], boa = BOA[c], sb = SBv[c];
            const int big = BIGF[c];
            const float v = a * xm + b;
            const float den = xm + boa;
            const float sden = (fabsf(den) > 1e-12f) ? den : 1e-12f;
            const int right = (v >= 0.f);
            const int jb = right ? c + 1 : c;
            const float xb = jb / 5.0f;
            const float ratio = (xb + boa) / sden;
            const float thit = big ? logf(fmaxf(ratio, 1e-12f)) / a : (xb - xm) / sb;
            const int valid = (fabsf(v) > 1e-12f) && (thit >= 0.f) && (!big || ratio > 0.f);
            if (!valid || thit >= 1.0f) {
                if (big) { const float ea = expf(a); C4 = ea; C2 = boa * (ea - 1.0f); }
                else     { C4 = 1.0f; C2 = b; }
                D2 = a;
            } else {
                const float s = 1.0f - thit;
                const float* Tc = right ? TR[jb] : TLm[jb];
                const float* Lc = right ? LRm[jb] : LLm[jb];
                int mm = 0;
                for (int m = 1; m <= 5; ++m) mm += (Tc[m] < s) ? 1 : 0;
                const float Lcum = Lc[mm], Tmm = Tc[mm];
                const int jb2 = right ? jb + mm : jb - mm;
                float P, Q;
                if (big) { FL = 1.0f; C0 = boa; P = logf(fabsf(xb + boa)) / a; Q = 1.0f / a; }
                else     { FL = 0.0f; C0 = 0.0f; P = xb / sb; Q = 1.0f / sb; }
                const float S0 = 1.0f - Tmm - P;
                const int absorbed = right ? (jb2 == 5) : (jb2 == 0);
                if (absorbed) {
                    C2 = right ? 1.0f : 0.0f;
                    D1 = -a * Q; D2 = a * P + Lcum;
                } else {
                    const int cc = right ? jb2 : jb2 - 1;
                    const float x0 = jb2 / 5.0f;
                    const float a2 = A[cc], b2 = Bc[cc];
                    if (fabsf(a2) > 1e-8f) {
                        const float boa2 = b2 / a2;
                        G = a2 * Q; C1 = (x0 + boa2) * expf(a2 * S0); C2 = -boa2;
                    } else {
                        C4 = b2 * Q; C2 = x0 + b2 * S0;
                    }
                    D1 = (a2 - a) * Q; D2 = a * P + Lcum + a2 * S0;
                }
            }
        }
        s_cf[tid * 2]     = make_float4(C0, G, C1, C4);
        s_cf[tid * 2 + 1] = make_float4(C2, D1, D2, FL);
    }
    __syncthreads();

    // ---- Phase E: build bin table ----
    for (int j = tid; j < NB; j += blockDim.x) {
        const float x0 = (float)j / FNB;
        const float x1 = (float)(j + 1) / FNB;
        float z0, l0, z1, l1;
        exact_eval(x0, z0, l0, s_thr, s_cf);
        exact_eval(x1, z1, l1, s_thr, s_cf);
        const int c = j / (NB / 5);
        bool mixed = false;
#pragma unroll
        for (int k = 0; k < 8; ++k) {
            const float t = s_thr[c * 8 + k];
            mixed = mixed || (t > x0 && t < x1);
        }
        float4 e;
        e.x = z0;
        e.y = mixed ? 1e30f : (z1 - z0);
        e.z = l0;
        e.w = mixed ? 0.0f : (l1 - l0);
        s_bin[j] = e;
    }
    __syncthreads();

    // ---- Phase F: stream points (simple grid-stride, float4) ----
    const int gtid   = blockIdx.x * blockDim.x + tid;
    const int stride = gridDim.x * blockDim.x;

    if ((n & 3) == 0) {
        const int n4 = n >> 2;
        const float4* __restrict__ x4 = (const float4*)xin;
        float4* __restrict__ z4 = (float4*)out;
        float4* __restrict__ l4 = (float4*)(out + n);
        for (int i = gtid; i < n4; i += stride) {
            const float4 xv = x4[i];
            float4 zv, lv;
            interp_point(xv.x, zv.x, lv.x, s_bin, s_thr, s_cf);
            interp_point(xv.y, zv.y, lv.y, s_bin, s_thr, s_cf);
            interp_point(xv.z, zv.z, lv.z, s_bin, s_thr, s_cf);
            interp_point(xv.w, zv.w, lv.w, s_bin, s_thr, s_cf);
            z4[i] = zv;
            l4[i] = lv;
        }
    } else {
        for (int i = gtid; i < n; i += stride) {
            float z, ld;
            interp_point(xin[i], z, ld, s_bin, s_thr, s_cf);
            out[i] = z;
            out[n + i] = ld;
        }
    }
}

extern "C" void kernel_launch(void* const* d_in, const int* in_sizes, int n_in,
                              void* d_out, int out_size)
{
    const float* x     = (const float*)d_in[0];
    const float* theta = (const float*)d_in[1];
    const float* Bm    = (const float*)d_in[2];
    float* out = (float*)d_out;
    const int n = in_sizes[0];

    // Grid = actual residency * SM count: exactly one wave, no stragglers.
    static int blocks_cached = 0;
    if (blocks_cached == 0) {
        int dev = 0, sms = 148, maxb = 5;
        cudaGetDevice(&dev);
        cudaDeviceGetAttribute(&sms, cudaDevAttrMultiProcessorCount, dev);
        cudaOccupancyMaxActiveBlocksPerMultiprocessor(&maxb, flowcpab_fused, 256, 0);
        if (maxb < 1) maxb = 1;
        blocks_cached = sms * maxb;
    }
    int blocks = blocks_cached;
    int work = ((n & 3) == 0) ? (n >> 2) : n;
    int maxneed = (work + 255) / 256;
    if (blocks > maxneed) blocks = maxneed;
    if (blocks < 1) blocks = 1;
    flowcpab_fused<<<blocks, 256>>>(x, theta, Bm, out, n);
}

// round 8
// speedup vs baseline: 2.1034x; 1.2089x over previous
#include <cuda_runtime.h>
#include <cuda_bf16.h>

// FlowCPAB: fully-branchless per-bin linear interpolation of the closed-form map.
// Each block rebuilds (in shared) the per-cell CPAB segment algebra
//   u = FL ? log|x+C0| : x;  z = C1*exp(G*u)+C4*u+C2;  ld = D1*u+D2
// then tabulates exact node values at 1281 bin edges and stores per-bin chords
// {z0, dz, ld0, dld}. Bins containing an ld-kink use the chord too (threshold
// snapped to bin edges): endpoints are exact, so the error is localized,
// <= |slope jump|*h/4 ~ 1e-4 absolute in ~10 of 1280 bins -- well under the
// 1e-3 tolerance. Stream loop: clamp, scale, one LDS.128, two FMA per point,
// no branches, two independent float4 chains per iteration (MLP=2).
// Grid sized to exactly (resident blocks/SM)*SMs: one wave (R6 lesson).

#define NC 5
#define EPSC 1e-7f
#define NB 1280              // 5 * 256 bins
#define FNB 1280.0f

__device__ __forceinline__ void exact_eval(float x, float& z, float& ld,
                                           const float* __restrict__ thr,
                                           const float4* __restrict__ cf)
{
    x = fminf(fmaxf(x, EPSC), 1.0f - EPSC);
    const int c = min(NC - 1, (int)(x * 5.0f));
    int mm = 0;
#pragma unroll
    for (int k = 0; k < 8; ++k) mm += (thr[c * 8 + k] < x) ? 1 : 0;
    const int seg = c * 9 + mm;
    const float4 c1 = cf[seg * 2];          // {C0, G, C1, C4}
    const float4 c2 = cf[seg * 2 + 1];      // {C2, D1, D2, FL}
    const float u = (c2.w != 0.0f) ? __logf(fabsf(x + c1.x)) : x;
    const float e = __expf(c1.y * u);
    z  = fmaf(c1.z, e, fmaf(c1.w, u, c2.x));
    ld = fmaf(c2.y, u, c2.z);
}

__device__ __forceinline__ void interp_point(float x, float& z, float& ld,
                                             const float4* __restrict__ s_bin)
{
    x = fminf(fmaxf(x, EPSC), 1.0f - EPSC);
    const float xf = x * FNB;
    const int bin = (int)xf;
    const float fr = xf - (float)bin;
    const float4 nb = s_bin[bin];
    z  = fmaf(fr, nb.y, nb.x);
    ld = fmaf(fr, nb.w, nb.z);
}

__global__ void __launch_bounds__(256, 8)
flowcpab_fused(const float* __restrict__ xin,
               const float* __restrict__ theta,
               const float* __restrict__ Bm,
               float* __restrict__ out, int n)
{
    __shared__ float  s_thr[NC * 8];
    __shared__ float4 s_cf[NC * 9 * 2];
    __shared__ float4 s_bin[NB];
    __shared__ float A[5], Bc[5], BOA[5], SBv[5];
    __shared__ int   BIGF[5];
    __shared__ float TAUR[5], TAUL[5], LDRv[5], LDLv[5];
    __shared__ float TR[6][6], TLm[6][6], LRm[6][6], LLm[6][6];
    __shared__ int   NT[5];

    const int tid = threadIdx.x;

    // ---- Phase A: per-cell (a,b) and traversal times ----
    if (tid < 5) {
        float a = 0.f, b = 0.f;
#pragma unroll
        for (int k = 0; k < 6; ++k) {
            a += Bm[(2 * tid) * 6 + k]     * theta[k];
            b += Bm[(2 * tid + 1) * 6 + k] * theta[k];
        }
        A[tid] = a; Bc[tid] = b;
        const int big = fabsf(a) > 1e-8f;
        BIGF[tid] = big;
        const float sa  = big ? a : 1.0f;
        const float sb  = (fabsf(b) > 1e-12f) ? b : 1e-12f;
        const float boa = b / sa;
        SBv[tid] = sb; BOA[tid] = boa;
        const float xl = tid / 5.0f, xr = (tid + 1) / 5.0f;
        {
            const float v = a * xl + b, den = xl + boa;
            const float sden = (fabsf(den) > 1e-12f) ? den : 1e-12f;
            const float ratio = (xr + boa) / sden;
            const float th = big ? logf(fmaxf(ratio, 1e-12f)) / sa : (xr - xl) / sb;
            const int valid = (fabsf(v) > 1e-12f) && (th >= 0.f) && (!big || ratio > 0.f);
            TAUR[tid] = valid ? th : 1e10f;
            LDRv[tid] = valid ? a * th : 0.f;
        }
        {
            const float v = a * xr + b, den = xr + boa;
            const float sden = (fabsf(den) > 1e-12f) ? den : 1e-12f;
            const float ratio = (xl + boa) / sden;
            const float th = big ? logf(fmaxf(ratio, 1e-12f)) / sa : (xl - xr) / sb;
            const int valid = (fabsf(v) > 1e-12f) && (th >= 0.f) && (!big || ratio > 0.f);
            TAUL[tid] = valid ? th : 1e10f;
            LDLv[tid] = valid ? a * th : 0.f;
        }
    }
    __syncthreads();

    // ---- Phase B: cumulative chain tables per boundary ----
    if (tid < 12) {
        const int j = tid % 6, dir = tid / 6;
        float tc = 0.f, lc = 0.f;
        if (dir == 0) {
            TR[j][0] = 0.f; LRm[j][0] = 0.f;
            for (int m = 1; m <= 5; ++m) {
                const int cell = j + m - 1;
                if (cell <= 4 && tc < 1e9f && TAUR[cell] < 1e9f) { tc += TAUR[cell]; lc += LDRv[cell]; }
                else tc = 1e10f;
                TR[j][m] = tc; LRm[j][m] = lc;
            }
        } else {
            TLm[j][0] = 0.f; LLm[j][0] = 0.f;
            for (int m = 1; m <= 5; ++m) {
                const int cell = j - m;
                if (cell >= 0 && tc < 1e9f && TAUL[cell] < 1e9f) { tc += TAUL[cell]; lc += LDLv[cell]; }
                else tc = 1e10f;
                TLm[j][m] = tc; LLm[j][m] = lc;
            }
        }
    }
    __syncthreads();

    // ---- Phase C: per-cell thresholds ----
    if (tid < 5) {
        const int c = tid;
        const float a = A[c], b = Bc[c], boa = BOA[c], sb = SBv[c];
        const int big = BIGF[c];
        const float xl = c / 5.0f, xr = (c + 1) / 5.0f;
        float cand[16]; int ncand = 0;
        if (big) {
            const float xs = -boa;
            if (xs > xl && xs < xr) cand[ncand++] = xs;
        }
        for (int dir = 0; dir < 2; ++dir) {
            const int jb = (dir == 0) ? c + 1 : c;
            const float xb = jb / 5.0f;
            const float* Tc = (dir == 0) ? TR[jb] : TLm[jb];
            for (int m = 0; m <= 5; ++m) {
                const float th = (m == 0) ? 1.0f : (1.0f - Tc[m]);
                if (!(th > 0.f && th <= 1.0f)) continue;
                const float xt = big ? (xb + boa) * expf(-a * th) - boa
                                     : xb - sb * th;
                if (xt > xl && xt < xr) {
                    const float v = a * xt + b;
                    const int r = (v >= 0.f);
                    if ((r && dir == 0) || (!r && dir == 1))
                        if (ncand < 16) cand[ncand++] = xt;
                }
            }
        }
        for (int i = 1; i < ncand; ++i) {
            float v = cand[i]; int j = i - 1;
            while (j >= 0 && cand[j] > v) { cand[j + 1] = cand[j]; --j; }
            cand[j + 1] = v;
        }
        int nt = 0;
        float last = -1.f;
        for (int i = 0; i < ncand && nt < 8; ++i)
            if (nt == 0 || cand[i] - last > 1e-9f) { last = cand[i]; s_thr[c * 8 + nt] = last; ++nt; }
        NT[c] = nt;
        for (int k = nt; k < 8; ++k) s_thr[c * 8 + k] = 1e30f;
    }
    __syncthreads();

    // ---- Phase D: per-segment coefficients ----
    if (tid < 45) {
        const int c = tid / 9, sgi = tid % 9;
        const int nt = NT[c];
        float C0 = 0, FL = 0, G = 0, C1 = 0, C4 = 0, C2 = 0, D1 = 0, D2 = 0;
        if (sgi <= nt) {
            const float xl = c / 5.0f, xr = (c + 1) / 5.0f;
            const float lo = (sgi == 0) ? xl : s_thr[c * 8 + sgi - 1];
            const float hi = (sgi == nt) ? xr : s_thr[c * 8 + sgi];
            const float xm = 0.5f * (lo + hi);
            const float a = A[c], b = Bc[c], boa = BOA[c], sb = SBv[c];
            const int big = BIGF[c];
            const float v = a * xm + b;
            const float den = xm + boa;
            const float sden = (fabsf(den) > 1e-12f) ? den : 1e-12f;
            const int right = (v >= 0.f);
            const int jb = right ? c + 1 : c;
            const float xb = jb / 5.0f;
            const float ratio = (xb + boa) / sden;
            const float thit = big ? logf(fmaxf(ratio, 1e-12f)) / a : (xb - xm) / sb;
            const int valid = (fabsf(v) > 1e-12f) && (thit >= 0.f) && (!big || ratio > 0.f);
            if (!valid || thit >= 1.0f) {
                if (big) { const float ea = expf(a); C4 = ea; C2 = boa * (ea - 1.0f); }
                else     { C4 = 1.0f; C2 = b; }
                D2 = a;
            } else {
                const float s = 1.0f - thit;
                const float* Tc = right ? TR[jb] : TLm[jb];
                const float* Lc = right ? LRm[jb] : LLm[jb];
                int mm = 0;
                for (int m = 1; m <= 5; ++m) mm += (Tc[m] < s) ? 1 : 0;
                const float Lcum = Lc[mm], Tmm = Tc[mm];
                const int jb2 = right ? jb + mm : jb - mm;
                float P, Q;
                if (big) { FL = 1.0f; C0 = boa; P = logf(fabsf(xb + boa)) / a; Q = 1.0f / a; }
                else     { FL = 0.0f; C0 = 0.0f; P = xb / sb; Q = 1.0f / sb; }
                const float S0 = 1.0f - Tmm - P;
                const int absorbed = right ? (jb2 == 5) : (jb2 == 0);
                if (absorbed) {
                    C2 = right ? 1.0f : 0.0f;
                    D1 = -a * Q; D2 = a * P + Lcum;
                } else {
                    const int cc = right ? jb2 : jb2 - 1;
                    const float x0 = jb2 / 5.0f;
                    const float a2 = A[cc], b2 = Bc[cc];
                    if (fabsf(a2) > 1e-8f) {
                        const float boa2 = b2 / a2;
                        G = a2 * Q; C1 = (x0 + boa2) * expf(a2 * S0); C2 = -boa2;
                    } else {
                        C4 = b2 * Q; C2 = x0 + b2 * S0;
                    }
                    D1 = (a2 - a) * Q; D2 = a * P + Lcum + a2 * S0;
                }
            }
        }
        s_cf[tid * 2]     = make_float4(C0, G, C1, C4);
        s_cf[tid * 2 + 1] = make_float4(C2, D1, D2, FL);
    }
    __syncthreads();

    // ---- Phase E: build pure-chord bin table (endpoints exact) ----
    for (int j = tid; j < NB; j += blockDim.x) {
        const float x0 = (float)j / FNB;
        const float x1 = (float)(j + 1) / FNB;
        float z0, l0, z1, l1;
        exact_eval(x0, z0, l0, s_thr, s_cf);
        exact_eval(x1, z1, l1, s_thr, s_cf);
        s_bin[j] = make_float4(z0, z1 - z0, l0, l1 - l0);
    }
    __syncthreads();

    // ---- Phase F: stream points, two independent float4 chains ----
    const int gtid   = blockIdx.x * blockDim.x + tid;
    const int stride = gridDim.x * blockDim.x;

    if ((n & 3) == 0) {
        const int n4 = n >> 2;
        const float4* __restrict__ x4 = (const float4*)xin;
        float4* __restrict__ z4 = (float4*)out;
        float4* __restrict__ l4 = (float4*)(out + n);

        int i = gtid;
        for (; i + stride < n4; i += 2 * stride) {
            const float4 xa = x4[i];
            const float4 xb = x4[i + stride];
            float4 za, la, zb, lb;
            interp_point(xa.x, za.x, la.x, s_bin);
            interp_point(xa.y, za.y, la.y, s_bin);
            interp_point(xa.z, za.z, la.z, s_bin);
            interp_point(xa.w, za.w, la.w, s_bin);
            interp_point(xb.x, zb.x, lb.x, s_bin);
            interp_point(xb.y, zb.y, lb.y, s_bin);
            interp_point(xb.z, zb.z, lb.z, s_bin);
            interp_point(xb.w, zb.w, lb.w, s_bin);
            z4[i] = za;            l4[i] = la;
            z4[i + stride] = zb;   l4[i + stride] = lb;
        }
        for (; i < n4; i += stride) {
            const float4 xv = x4[i];
            float4 zv, lv;
            interp_point(xv.x, zv.x, lv.x, s_bin);
            interp_point(xv.y, zv.y, lv.y, s_bin);
            interp_point(xv.z, zv.z, lv.z, s_bin);
            interp_point(xv.w, zv.w, lv.w, s_bin);
            z4[i] = zv;
            l4[i] = lv;
        }
    } else {
        for (int i = gtid; i < n; i += stride) {
            float z, ld;
            interp_point(xin[i], z, ld, s_bin);
            out[i] = z;
            out[n + i] = ld;
        }
    }
}

extern "C" void kernel_launch(void* const* d_in, const int* in_sizes, int n_in,
                              void* d_out, int out_size)
{
    const float* x     = (const float*)d_in[0];
    const float* theta = (const float*)d_in[1];
    const float* Bm    = (const float*)d_in[2];
    float* out = (float*)d_out;
    const int n = in_sizes[0];

    // Grid = actual residency * SM count: exactly one wave.
    static int blocks_cached = 0;
    if (blocks_cached == 0) {
        int dev = 0, sms = 148, maxb = 8;
        cudaGetDevice(&dev);
        cudaDeviceGetAttribute(&sms, cudaDevAttrMultiProcessorCount, dev);
        cudaOccupancyMaxActiveBlocksPerMultiprocessor(&maxb, flowcpab_fused, 256, 0);
        if (maxb < 1) maxb = 1;
        blocks_cached = sms * maxb;
    }
    int blocks = blocks_cached;
    int work = ((n & 3) == 0) ? (n >> 2) : n;
    int maxneed = (work + 255) / 256;
    if (blocks > maxneed) blocks = maxneed;
    if (blocks < 1) blocks = 1;
    flowcpab_fused<<<blocks, 256>>>(x, theta, Bm, out, n);
}

// round 9
// speedup vs baseline: 2.1152x; 1.0056x over previous
#include <cuda_runtime.h>
#include <cuda_bf16.h>

// FlowCPAB: fully-branchless per-bin linear interpolation of the closed-form map.
// Each block rebuilds (in shared) the per-cell CPAB segment algebra
//   u = FL ? log|x+C0| : x;  z = C1*exp(G*u)+C4*u+C2;  ld = D1*u+D2
// then tabulates exact node values at 1281 bin edges and stores per-bin chords
// {z0, dz, ld0, dld}. Kink bins use the chord too (endpoints exact, localized
// error ~1e-4 abs in ~10/1280 bins, well under 1e-3 tolerance).
// Stream loop: 4 independent float4 chains per iteration (MLP=4 LDG.128),
// per point: clamp, scale, one LDS.128, two FMA. Grid sized at runtime to
// exactly (resident blocks/SM)*SMs: one wave (R6 lesson).

#define NC 5
#define EPSC 1e-7f
#define NB 1280              // 5 * 256 bins
#define FNB 1280.0f

__device__ __forceinline__ void exact_eval(float x, float& z, float& ld,
                                           const float* __restrict__ thr,
                                           const float4* __restrict__ cf)
{
    x = fminf(fmaxf(x, EPSC), 1.0f - EPSC);
    const int c = min(NC - 1, (int)(x * 5.0f));
    int mm = 0;
#pragma unroll
    for (int k = 0; k < 8; ++k) mm += (thr[c * 8 + k] < x) ? 1 : 0;
    const int seg = c * 9 + mm;
    const float4 c1 = cf[seg * 2];          // {C0, G, C1, C4}
    const float4 c2 = cf[seg * 2 + 1];      // {C2, D1, D2, FL}
    const float u = (c2.w != 0.0f) ? __logf(fabsf(x + c1.x)) : x;
    const float e = __expf(c1.y * u);
    z  = fmaf(c1.z, e, fmaf(c1.w, u, c2.x));
    ld = fmaf(c2.y, u, c2.z);
}

__device__ __forceinline__ void interp_point(float x, float& z, float& ld,
                                             const float4* __restrict__ s_bin)
{
    x = fminf(fmaxf(x, EPSC), 1.0f - EPSC);
    const float xf = x * FNB;
    const int bin = (int)xf;
    const float fr = xf - (float)bin;
    const float4 nb = s_bin[bin];
    z  = fmaf(fr, nb.y, nb.x);
    ld = fmaf(fr, nb.w, nb.z);
}

__device__ __forceinline__ void interp_quad(const float4 xv, float4& zv, float4& lv,
                                            const float4* __restrict__ s_bin)
{
    interp_point(xv.x, zv.x, lv.x, s_bin);
    interp_point(xv.y, zv.y, lv.y, s_bin);
    interp_point(xv.z, zv.z, lv.z, s_bin);
    interp_point(xv.w, zv.w, lv.w, s_bin);
}

__global__ void __launch_bounds__(256, 6)
flowcpab_fused(const float* __restrict__ xin,
               const float* __restrict__ theta,
               const float* __restrict__ Bm,
               float* __restrict__ out, int n)
{
    __shared__ float  s_thr[NC * 8];
    __shared__ float4 s_cf[NC * 9 * 2];
    __shared__ float4 s_bin[NB];
    __shared__ float A[5], Bc[5], BOA[5], SBv[5];
    __shared__ int   BIGF[5];
    __shared__ float TAUR[5], TAUL[5], LDRv[5], LDLv[5];
    __shared__ float TR[6][6], TLm[6][6], LRm[6][6], LLm[6][6];
    __shared__ int   NT[5];

    const int tid = threadIdx.x;

    // ---- Phase A: per-cell (a,b) and traversal times ----
    if (tid < 5) {
        float a = 0.f, b = 0.f;
#pragma unroll
        for (int k = 0; k < 6; ++k) {
            a += Bm[(2 * tid) * 6 + k]     * theta[k];
            b += Bm[(2 * tid + 1) * 6 + k] * theta[k];
        }
        A[tid] = a; Bc[tid] = b;
        const int big = fabsf(a) > 1e-8f;
        BIGF[tid] = big;
        const float sa  = big ? a : 1.0f;
        const float sb  = (fabsf(b) > 1e-12f) ? b : 1e-12f;
        const float boa = b / sa;
        SBv[tid] = sb; BOA[tid] = boa;
        const float xl = tid / 5.0f, xr = (tid + 1) / 5.0f;
        {
            const float v = a * xl + b, den = xl + boa;
            const float sden = (fabsf(den) > 1e-12f) ? den : 1e-12f;
            const float ratio = (xr + boa) / sden;
            const float th = big ? logf(fmaxf(ratio, 1e-12f)) / sa : (xr - xl) / sb;
            const int valid = (fabsf(v) > 1e-12f) && (th >= 0.f) && (!big || ratio > 0.f);
            TAUR[tid] = valid ? th : 1e10f;
            LDRv[tid] = valid ? a * th : 0.f;
        }
        {
            const float v = a * xr + b, den = xr + boa;
            const float sden = (fabsf(den) > 1e-12f) ? den : 1e-12f;
            const float ratio = (xl + boa) / sden;
            const float th = big ? logf(fmaxf(ratio, 1e-12f)) / sa : (xl - xr) / sb;
            const int valid = (fabsf(v) > 1e-12f) && (th >= 0.f) && (!big || ratio > 0.f);
            TAUL[tid] = valid ? th : 1e10f;
            LDLv[tid] = valid ? a * th : 0.f;
        }
    }
    __syncthreads();

    // ---- Phase B: cumulative chain tables per boundary ----
    if (tid < 12) {
        const int j = tid % 6, dir = tid / 6;
        float tc = 0.f, lc = 0.f;
        if (dir == 0) {
            TR[j][0] = 0.f; LRm[j][0] = 0.f;
            for (int m = 1; m <= 5; ++m) {
                const int cell = j + m - 1;
                if (cell <= 4 && tc < 1e9f && TAUR[cell] < 1e9f) { tc += TAUR[cell]; lc += LDRv[cell]; }
                else tc = 1e10f;
                TR[j][m] = tc; LRm[j][m] = lc;
            }
        } else {
            TLm[j][0] = 0.f; LLm[j][0] = 0.f;
            for (int m = 1; m <= 5; ++m) {
                const int cell = j - m;
                if (cell >= 0 && tc < 1e9f && TAUL[cell] < 1e9f) { tc += TAUL[cell]; lc += LDLv[cell]; }
                else tc = 1e10f;
                TLm[j][m] = tc; LLm[j][m] = lc;
            }
        }
    }
    __syncthreads();

    // ---- Phase C: per-cell thresholds ----
    if (tid < 5) {
        const int c = tid;
        const float a = A[c], b = Bc[c], boa = BOA[c], sb = SBv[c];
        const int big = BIGF[c];
        const float xl = c / 5.0f, xr = (c + 1) / 5.0f;
        float cand[16]; int ncand = 0;
        if (big) {
            const float xs = -boa;
            if (xs > xl && xs < xr) cand[ncand++] = xs;
        }
        for (int dir = 0; dir < 2; ++dir) {
            const int jb = (dir == 0) ? c + 1 : c;
            const float xb = jb / 5.0f;
            const float* Tc = (dir == 0) ? TR[jb] : TLm[jb];
            for (int m = 0; m <= 5; ++m) {
                const float th = (m == 0) ? 1.0f : (1.0f - Tc[m]);
                if (!(th > 0.f && th <= 1.0f)) continue;
                const float xt = big ? (xb + boa) * expf(-a * th) - boa
                                     : xb - sb * th;
                if (xt > xl && xt < xr) {
                    const float v = a * xt + b;
                    const int r = (v >= 0.f);
                    if ((r && dir == 0) || (!r && dir == 1))
                        if (ncand < 16) cand[ncand++] = xt;
                }
            }
        }
        for (int i = 1; i < ncand; ++i) {
            float v = cand[i]; int j = i - 1;
            while (j >= 0 && cand[j] > v) { cand[j + 1] = cand[j]; --j; }
            cand[j + 1] = v;
        }
        int nt = 0;
        float last = -1.f;
        for (int i = 0; i < ncand && nt < 8; ++i)
            if (nt == 0 || cand[i] - last > 1e-9f) { last = cand[i]; s_thr[c * 8 + nt] = last; ++nt; }
        NT[c] = nt;
        for (int k = nt; k < 8; ++k) s_thr[c * 8 + k] = 1e30f;
    }
    __syncthreads();

    // ---- Phase D: per-segment coefficients ----
    if (tid < 45) {
        const int c = tid / 9, sgi = tid % 9;
        const int nt = NT[c];
        float C0 = 0, FL = 0, G = 0, C1 = 0, C4 = 0, C2 = 0, D1 = 0, D2 = 0;
        if (sgi <= nt) {
            const float xl = c / 5.0f, xr = (c + 1) / 5.0f;
            const float lo = (sgi == 0) ? xl : s_thr[c * 8 + sgi - 1];
            const float hi = (sgi == nt) ? xr : s_thr[c * 8 + sgi];
            const float xm = 0.5f * (lo + hi);
            const float a = A[c], b = Bc[c], boa = BOA[c], sb = SBv[c];
            const int big = BIGF[c];
            const float v = a * xm + b;
            const float den = xm + boa;
            const float sden = (fabsf(den) > 1e-12f) ? den : 1e-12f;
            const int right = (v >= 0.f);
            const int jb = right ? c + 1 : c;
            const float xb = jb / 5.0f;
            const float ratio = (xb + boa) / sden;
            const float thit = big ? logf(fmaxf(ratio, 1e-12f)) / a : (xb - xm) / sb;
            const int valid = (fabsf(v) > 1e-12f) && (thit >= 0.f) && (!big || ratio > 0.f);
            if (!valid || thit >= 1.0f) {
                if (big) { const float ea = expf(a); C4 = ea; C2 = boa * (ea - 1.0f); }
                else     { C4 = 1.0f; C2 = b; }
                D2 = a;
            } else {
                const float s = 1.0f - thit;
                const float* Tc = right ? TR[jb] : TLm[jb];
                const float* Lc = right ? LRm[jb] : LLm[jb];
                int mm = 0;
                for (int m = 1; m <= 5; ++m) mm += (Tc[m] < s) ? 1 : 0;
                const float Lcum = Lc[mm], Tmm = Tc[mm];
                const int jb2 = right ? jb + mm : jb - mm;
                float P, Q;
                if (big) { FL = 1.0f; C0 = boa; P = logf(fabsf(xb + boa)) / a; Q = 1.0f / a; }
                else     { FL = 0.0f; C0 = 0.0f; P = xb / sb; Q = 1.0f / sb; }
                const float S0 = 1.0f - Tmm - P;
                const int absorbed = right ? (jb2 == 5) : (jb2 == 0);
                if (absorbed) {
                    C2 = right ? 1.0f : 0.0f;
                    D1 = -a * Q; D2 = a * P + Lcum;
                } else {
                    const int cc = right ? jb2 : jb2 - 1;
                    const float x0 = jb2 / 5.0f;
                    const float a2 = A[cc], b2 = Bc[cc];
                    if (fabsf(a2) > 1e-8f) {
                        const float boa2 = b2 / a2;
                        G = a2 * Q; C1 = (x0 + boa2) * expf(a2 * S0); C2 = -boa2;
                    } else {
                        C4 = b2 * Q; C2 = x0 + b2 * S0;
                    }
                    D1 = (a2 - a) * Q; D2 = a * P + Lcum + a2 * S0;
                }
            }
        }
        s_cf[tid * 2]     = make_float4(C0, G, C1, C4);
        s_cf[tid * 2 + 1] = make_float4(C2, D1, D2, FL);
    }
    __syncthreads();

    // ---- Phase E: build pure-chord bin table (endpoints exact) ----
    for (int j = tid; j < NB; j += blockDim.x) {
        const float x0 = (float)j / FNB;
        const float x1 = (float)(j + 1) / FNB;
        float z0, l0, z1, l1;
        exact_eval(x0, z0, l0, s_thr, s_cf);
        exact_eval(x1, z1, l1, s_thr, s_cf);
        s_bin[j] = make_float4(z0, z1 - z0, l0, l1 - l0);
    }
    __syncthreads();

    // ---- Phase F: stream points, four independent float4 chains (MLP=4) ----
    const int gtid   = blockIdx.x * blockDim.x + tid;
    const int stride = gridDim.x * blockDim.x;

    if ((n & 3) == 0) {
        const int n4 = n >> 2;
        const float4* __restrict__ x4 = (const float4*)xin;
        float4* __restrict__ z4 = (float4*)out;
        float4* __restrict__ l4 = (float4*)(out + n);

        int i = gtid;
        for (; i + 3 * stride < n4; i += 4 * stride) {
            // all four loads issued before any consumer
            const float4 xa = x4[i];
            const float4 xb = x4[i + stride];
            const float4 xc = x4[i + 2 * stride];
            const float4 xd = x4[i + 3 * stride];
            float4 zv, lv;
            interp_quad(xa, zv, lv, s_bin);
            z4[i] = zv;                l4[i] = lv;
            interp_quad(xb, zv, lv, s_bin);
            z4[i + stride] = zv;       l4[i + stride] = lv;
            interp_quad(xc, zv, lv, s_bin);
            z4[i + 2 * stride] = zv;   l4[i + 2 * stride] = lv;
            interp_quad(xd, zv, lv, s_bin);
            z4[i + 3 * stride] = zv;   l4[i + 3 * stride] = lv;
        }
        for (; i < n4; i += stride) {
            const float4 xv = x4[i];
            float4 zv, lv;
            interp_quad(xv, zv, lv, s_bin);
            z4[i] = zv;
            l4[i] = lv;
        }
    } else {
        for (int i = gtid; i < n; i += stride) {
            float z, ld;
            interp_point(xin[i], z, ld, s_bin);
            out[i] = z;
            out[n + i] = ld;
        }
    }
}

extern "C" void kernel_launch(void* const* d_in, const int* in_sizes, int n_in,
                              void* d_out, int out_size)
{
    const float* x     = (const float*)d_in[0];
    const float* theta = (const float*)d_in[1];
    const float* Bm    = (const float*)d_in[2];
    float* out = (float*)d_out;
    const int n = in_sizes[0];

    // Grid = actual residency * SM count: exactly one wave.
    static int blocks_cached = 0;
    if (blocks_cached == 0) {
        int dev = 0, sms = 148, maxb = 6;
        cudaGetDevice(&dev);
        cudaDeviceGetAttribute(&sms, cudaDevAttrMultiProcessorCount, dev);
        cudaOccupancyMaxActiveBlocksPerMultiprocessor(&maxb, flowcpab_fused, 256, 0);
        if (maxb < 1) maxb = 1;
        blocks_cached = sms * maxb;
    }
    int blocks = blocks_cached;
    int work = ((n & 3) == 0) ? (n >> 2) : n;
    int maxneed = (work + 255) / 256;
    if (blocks > maxneed) blocks = maxneed;
    if (blocks < 1) blocks = 1;
    flowcpab_fused<<<blocks, 256>>>(x, theta, Bm, out, n);
}

// round 10
// speedup vs baseline: 2.1363x; 1.0099x over previous
#include <cuda_runtime.h>
#include <cuda_bf16.h>

// FlowCPAB: fully-branchless per-bin linear interpolation of the closed-form map.
// Per-block setup rebuilds the CPAB segment algebra in shared, then tabulates
// exact node values at 1281 bin edges (each node evaluated ONCE, differenced in
// a second pass) and stores per-bin chords {z0,dz,ld0,dld}. Stream loop:
// clamp, scale, one LDS.128, two FMA per point; 4 independent float4 chains.
// All setup transcendentals are MUFU intrinsics (__logf/__expf): thresholds are
// continuity points of (z,ld), so 1e-7-level shifts are harmless.
// Grid sized at runtime to exactly (resident blocks/SM)*SMs: one wave.

#define NC 5
#define EPSC 1e-7f
#define NB 1280              // 5 * 256 bins
#define FNB 1280.0f

__device__ __forceinline__ void exact_eval(float x, float& z, float& ld,
                                           const float* __restrict__ thr,
                                           const float4* __restrict__ cf)
{
    x = fminf(fmaxf(x, EPSC), 1.0f - EPSC);
    const int c = min(NC - 1, (int)(x * 5.0f));
    int mm = 0;
#pragma unroll
    for (int k = 0; k < 8; ++k) mm += (thr[c * 8 + k] < x) ? 1 : 0;
    const int seg = c * 9 + mm;
    const float4 c1 = cf[seg * 2];          // {C0, G, C1, C4}
    const float4 c2 = cf[seg * 2 + 1];      // {C2, D1, D2, FL}
    const float u = (c2.w != 0.0f) ? __logf(fabsf(x + c1.x)) : x;
    const float e = __expf(c1.y * u);
    z  = fmaf(c1.z, e, fmaf(c1.w, u, c2.x));
    ld = fmaf(c2.y, u, c2.z);
}

__device__ __forceinline__ void interp_point(float x, float& z, float& ld,
                                             const float4* __restrict__ s_bin)
{
    x = fminf(fmaxf(x, EPSC), 1.0f - EPSC);
    const float xf = x * FNB;
    const int bin = (int)xf;
    const float fr = xf - (float)bin;
    const float4 nb = s_bin[bin];
    z  = fmaf(fr, nb.y, nb.x);
    ld = fmaf(fr, nb.w, nb.z);
}

__device__ __forceinline__ void interp_quad(const float4 xv, float4& zv, float4& lv,
                                            const float4* __restrict__ s_bin)
{
    interp_point(xv.x, zv.x, lv.x, s_bin);
    interp_point(xv.y, zv.y, lv.y, s_bin);
    interp_point(xv.z, zv.z, lv.z, s_bin);
    interp_point(xv.w, zv.w, lv.w, s_bin);
}

__global__ void __launch_bounds__(256, 6)
flowcpab_fused(const float* __restrict__ xin,
               const float* __restrict__ theta,
               const float* __restrict__ Bm,
               float* __restrict__ out, int n)
{
    __shared__ float  s_thr[NC * 8];
    __shared__ float4 s_cf[NC * 9 * 2];
    __shared__ float4 s_bin[NB];
    __shared__ float2 s_last;            // node NB (x = 1.0)
    __shared__ float A[5], Bc[5], BOA[5], SBv[5];
    __shared__ int   BIGF[5];
    __shared__ float TAUR[5], TAUL[5], LDRv[5], LDLv[5];
    __shared__ float TR[6][6], TLm[6][6], LRm[6][6], LLm[6][6];
    __shared__ int   NT[5];

    const int tid = threadIdx.x;

    // ---- Phase A: per-cell (a,b) and traversal times ----
    if (tid < 5) {
        float a = 0.f, b = 0.f;
#pragma unroll
        for (int k = 0; k < 6; ++k) {
            a += Bm[(2 * tid) * 6 + k]     * theta[k];
            b += Bm[(2 * tid + 1) * 6 + k] * theta[k];
        }
        A[tid] = a; Bc[tid] = b;
        const int big = fabsf(a) > 1e-8f;
        BIGF[tid] = big;
        const float sa  = big ? a : 1.0f;
        const float sb  = (fabsf(b) > 1e-12f) ? b : 1e-12f;
        const float boa = b / sa;
        SBv[tid] = sb; BOA[tid] = boa;
        const float xl = tid / 5.0f, xr = (tid + 1) / 5.0f;
        {
            const float v = a * xl + b, den = xl + boa;
            const float sden = (fabsf(den) > 1e-12f) ? den : 1e-12f;
            const float ratio = (xr + boa) / sden;
            const float th = big ? __logf(fmaxf(ratio, 1e-12f)) / sa : (xr - xl) / sb;
            const int valid = (fabsf(v) > 1e-12f) && (th >= 0.f) && (!big || ratio > 0.f);
            TAUR[tid] = valid ? th : 1e10f;
            LDRv[tid] = valid ? a * th : 0.f;
        }
        {
            const float v = a * xr + b, den = xr + boa;
            const float sden = (fabsf(den) > 1e-12f) ? den : 1e-12f;
            const float ratio = (xl + boa) / sden;
            const float th = big ? __logf(fmaxf(ratio, 1e-12f)) / sa : (xl - xr) / sb;
            const int valid = (fabsf(v) > 1e-12f) && (th >= 0.f) && (!big || ratio > 0.f);
            TAUL[tid] = valid ? th : 1e10f;
            LDLv[tid] = valid ? a * th : 0.f;
        }
    }
    __syncthreads();

    // ---- Phase B: cumulative chain tables per boundary ----
    if (tid < 12) {
        const int j = tid % 6, dir = tid / 6;
        float tc = 0.f, lc = 0.f;
        if (dir == 0) {
            TR[j][0] = 0.f; LRm[j][0] = 0.f;
            for (int m = 1; m <= 5; ++m) {
                const int cell = j + m - 1;
                if (cell <= 4 && tc < 1e9f && TAUR[cell] < 1e9f) { tc += TAUR[cell]; lc += LDRv[cell]; }
                else tc = 1e10f;
                TR[j][m] = tc; LRm[j][m] = lc;
            }
        } else {
            TLm[j][0] = 0.f; LLm[j][0] = 0.f;
            for (int m = 1; m <= 5; ++m) {
                const int cell = j - m;
                if (cell >= 0 && tc < 1e9f && TAUL[cell] < 1e9f) { tc += TAUL[cell]; lc += LDLv[cell]; }
                else tc = 1e10f;
                TLm[j][m] = tc; LLm[j][m] = lc;
            }
        }
    }
    __syncthreads();

    // ---- Phase C: per-cell thresholds (12 candidates spread across 12 threads
    //      per cell would add syncs; keep per-cell serial but with MUFU exp) ----
    if (tid < 5) {
        const int c = tid;
        const float a = A[c], b = Bc[c], boa = BOA[c], sb = SBv[c];
        const int big = BIGF[c];
        const float xl = c / 5.0f, xr = (c + 1) / 5.0f;
        float cand[16]; int ncand = 0;
        if (big) {
            const float xs = -boa;
            if (xs > xl && xs < xr) cand[ncand++] = xs;
        }
        for (int dir = 0; dir < 2; ++dir) {
            const int jb = (dir == 0) ? c + 1 : c;
            const float xb = jb / 5.0f;
            const float* Tc = (dir == 0) ? TR[jb] : TLm[jb];
            for (int m = 0; m <= 5; ++m) {
                const float th = (m == 0) ? 1.0f : (1.0f - Tc[m]);
                if (!(th > 0.f && th <= 1.0f)) continue;
                const float xt = big ? (xb + boa) * __expf(-a * th) - boa
                                     : xb - sb * th;
                if (xt > xl && xt < xr) {
                    const float v = a * xt + b;
                    const int r = (v >= 0.f);
                    if ((r && dir == 0) || (!r && dir == 1))
                        if (ncand < 16) cand[ncand++] = xt;
                }
            }
        }
        for (int i = 1; i < ncand; ++i) {
            float v = cand[i]; int j = i - 1;
            while (j >= 0 && cand[j] > v) { cand[j + 1] = cand[j]; --j; }
            cand[j + 1] = v;
        }
        int nt = 0;
        float last = -1.f;
        for (int i = 0; i < ncand && nt < 8; ++i)
            if (nt == 0 || cand[i] - last > 1e-9f) { last = cand[i]; s_thr[c * 8 + nt] = last; ++nt; }
        NT[c] = nt;
        for (int k = nt; k < 8; ++k) s_thr[c * 8 + k] = 1e30f;
    }
    __syncthreads();

    // ---- Phase D: per-segment coefficients ----
    if (tid < 45) {
        const int c = tid / 9, sgi = tid % 9;
        const int nt = NT[c];
        float C0 = 0, FL = 0, G = 0, C1 = 0, C4 = 0, C2 = 0, D1 = 0, D2 = 0;
        if (sgi <= nt) {
            const float xl = c / 5.0f, xr = (c + 1) / 5.0f;
            const float lo = (sgi == 0) ? xl : s_thr[c * 8 + sgi - 1];
            const float hi = (sgi == nt) ? xr : s_thr[c * 8 + sgi];
            const float xm = 0.5f * (lo + hi);
            const float a = A[c], b = Bc[c], boa = BOA[c], sb = SBv[c];
            const int big = BIGF[c];
            const float v = a * xm + b;
            const float den = xm + boa;
            const float sden = (fabsf(den) > 1e-12f) ? den : 1e-12f;
            const int right = (v >= 0.f);
            const int jb = right ? c + 1 : c;
            const float xb = jb / 5.0f;
            const float ratio = (xb + boa) / sden;
            const float thit = big ? __logf(fmaxf(ratio, 1e-12f)) / a : (xb - xm) / sb;
            const int valid = (fabsf(v) > 1e-12f) && (thit >= 0.f) && (!big || ratio > 0.f);
            if (!valid || thit >= 1.0f) {
                if (big) { const float ea = __expf(a); C4 = ea; C2 = boa * (ea - 1.0f); }
                else     { C4 = 1.0f; C2 = b; }
                D2 = a;
            } else {
                const float s = 1.0f - thit;
                const float* Tc = right ? TR[jb] : TLm[jb];
                const float* Lc = right ? LRm[jb] : LLm[jb];
                int mm = 0;
                for (int m = 1; m <= 5; ++m) mm += (Tc[m] < s) ? 1 : 0;
                const float Lcum = Lc[mm], Tmm = Tc[mm];
                const int jb2 = right ? jb + mm : jb - mm;
                float P, Q;
                if (big) { FL = 1.0f; C0 = boa; P = __logf(fabsf(xb + boa)) / a; Q = 1.0f / a; }
                else     { FL = 0.0f; C0 = 0.0f; P = xb / sb; Q = 1.0f / sb; }
                const float S0 = 1.0f - Tmm - P;
                const int absorbed = right ? (jb2 == 5) : (jb2 == 0);
                if (absorbed) {
                    C2 = right ? 1.0f : 0.0f;
                    D1 = -a * Q; D2 = a * P + Lcum;
                } else {
                    const int cc = right ? jb2 : jb2 - 1;
                    const float x0 = jb2 / 5.0f;
                    const float a2 = A[cc], b2 = Bc[cc];
                    if (fabsf(a2) > 1e-8f) {
                        const float boa2 = b2 / a2;
                        G = a2 * Q; C1 = (x0 + boa2) * __expf(a2 * S0); C2 = -boa2;
                    } else {
                        C4 = b2 * Q; C2 = x0 + b2 * S0;
                    }
                    D1 = (a2 - a) * Q; D2 = a * P + Lcum + a2 * S0;
                }
            }
        }
        s_cf[tid * 2]     = make_float4(C0, G, C1, C4);
        s_cf[tid * 2 + 1] = make_float4(C2, D1, D2, FL);
    }
    __syncthreads();

    // ---- Phase E1: evaluate each node ONCE into s_bin[j].{x,z} ----
    for (int j = tid; j < NB; j += blockDim.x) {
        float z0, l0;
        exact_eval((float)j / FNB, z0, l0, s_thr, s_cf);
        s_bin[j].x = z0;
        s_bin[j].z = l0;
    }
    if (tid == 0) {
        float z1, l1;
        exact_eval(1.0f, z1, l1, s_thr, s_cf);
        s_last = make_float2(z1, l1);
    }
    __syncthreads();

    // ---- Phase E2: difference neighbors into .{y,w} (reads .x/.z only) ----
    for (int j = tid; j < NB; j += blockDim.x) {
        float zn, ln;
        if (j + 1 < NB) { zn = s_bin[j + 1].x; ln = s_bin[j + 1].z; }
        else            { zn = s_last.x;       ln = s_last.y; }
        s_bin[j].y = zn - s_bin[j].x;
        s_bin[j].w = ln - s_bin[j].z;
    }
    __syncthreads();

    // ---- Phase F: stream points, four independent float4 chains (MLP=4) ----
    const int gtid   = blockIdx.x * blockDim.x + tid;
    const int stride = gridDim.x * blockDim.x;

    if ((n & 3) == 0) {
        const int n4 = n >> 2;
        const float4* __restrict__ x4 = (const float4*)xin;
        float4* __restrict__ z4 = (float4*)out;
        float4* __restrict__ l4 = (float4*)(out + n);

        int i = gtid;
        for (; i + 3 * stride < n4; i += 4 * stride) {
            const float4 xa = __ldcs(&x4[i]);
            const float4 xb = __ldcs(&x4[i + stride]);
            const float4 xc = __ldcs(&x4[i + 2 * stride]);
            const float4 xd = __ldcs(&x4[i + 3 * stride]);
            float4 zv, lv;
            interp_quad(xa, zv, lv, s_bin);
            __stcs(&z4[i], zv);                __stcs(&l4[i], lv);
            interp_quad(xb, zv, lv, s_bin);
            __stcs(&z4[i + stride], zv);       __stcs(&l4[i + stride], lv);
            interp_quad(xc, zv, lv, s_bin);
            __stcs(&z4[i + 2 * stride], zv);   __stcs(&l4[i + 2 * stride], lv);
            interp_quad(xd, zv, lv, s_bin);
            __stcs(&z4[i + 3 * stride], zv);   __stcs(&l4[i + 3 * stride], lv);
        }
        for (; i < n4; i += stride) {
            const float4 xv = __ldcs(&x4[i]);
            float4 zv, lv;
            interp_quad(xv, zv, lv, s_bin);
            __stcs(&z4[i], zv);
            __stcs(&l4[i], lv);
        }
    } else {
        for (int i = gtid; i < n; i += stride) {
            float z, ld;
            interp_point(xin[i], z, ld, s_bin);
            out[i] = z;
            out[n + i] = ld;
        }
    }
}

extern "C" void kernel_launch(void* const* d_in, const int* in_sizes, int n_in,
                              void* d_out, int out_size)
{
    const float* x     = (const float*)d_in[0];
    const float* theta = (const float*)d_in[1];
    const float* Bm    = (const float*)d_in[2];
    float* out = (float*)d_out;
    const int n = in_sizes[0];

    // Grid = actual residency * SM count: exactly one wave.
    static int blocks_cached = 0;
    if (blocks_cached == 0) {
        int dev = 0, sms = 148, maxb = 6;
        cudaGetDevice(&dev);
        cudaDeviceGetAttribute(&sms, cudaDevAttrMultiProcessorCount, dev);
        cudaOccupancyMaxActiveBlocksPerMultiprocessor(&maxb, flowcpab_fused, 256, 0);
        if (maxb < 1) maxb = 1;
        blocks_cached = sms * maxb;
    }
    int blocks = blocks_cached;
    int work = ((n & 3) == 0) ? (n >> 2) : n;
    int maxneed = (work + 255) / 256;
    if (blocks > maxneed) blocks = maxneed;
    if (blocks < 1) blocks = 1;
    flowcpab_fused<<<blocks, 256>>>(x, theta, Bm, out, n);
}